// round 8
// baseline (speedup 1.0000x reference)
#include <cuda_runtime.h>
#include <cstdint>
#include <math.h>

#define BB 32
#define LD 256
#define LP 1024
#define NH 8

// ---- scratch (device globals; allocations forbidden) ----
__device__ float g_rd [(size_t)BB*LD*512];     // rounded drug
__device__ float g_rp [(size_t)BB*LP*512];     // rounded protein
__device__ float g_W  [(size_t)8*512*512];     // rounded weights
__device__ float g_QKd[(size_t)256*LD*128];    // [bh][q][Qd|Kd] scaled, rounded
__device__ float g_KQp[(size_t)256*LP*128];    // [bh][p][Kp|Qp] rounded
__device__ float g_Vd [(size_t)256*LD*64];     // rounded
__device__ float g_Vp [(size_t)256*LP*64];     // rounded
__device__ float g_aR [(size_t)256*LD*LP];     // rounded attn
__device__ float g_cd [(size_t)BB*LD*512];     // rounded ctx_d
__device__ float g_cp [(size_t)BB*LP*512];     // rounded ctx_p

__device__ __forceinline__ float rtf(float x){
    uint32_t u = __float_as_uint(x);
    return __uint_as_float((u + 0x1000u) & 0xFFFFE000u);
}
__device__ __forceinline__ void cp16(void* s, const void* g){
    uint32_t sa = (uint32_t)__cvta_generic_to_shared(s);
    asm volatile("cp.async.cg.shared.global [%0], [%1], 16;\n" :: "r"(sa), "l"(g));
}
#define CP_COMMIT asm volatile("cp.async.commit_group;\n")
#define CP_WAIT1  asm volatile("cp.async.wait_group 1;\n")

__device__ __forceinline__ void mma8(float* c, const uint32_t* a, uint32_t b0, uint32_t b1){
    asm volatile("mma.sync.aligned.m16n8k8.row.col.f32.tf32.tf32.f32 "
        "{%0,%1,%2,%3}, {%4,%5,%6,%7}, {%8,%9}, {%0,%1,%2,%3};\n"
        : "+f"(c[0]), "+f"(c[1]), "+f"(c[2]), "+f"(c[3])
        : "r"(a[0]), "r"(a[1]), "r"(a[2]), "r"(a[3]), "r"(b0), "r"(b1));
}
__device__ __forceinline__ float fexp(float x){
    x = fmaxf(x, -80.0f);
    float t = x * 1.44269504089f;
    float n = rintf(t);
    float f = t - n;
    float p =           1.33336621e-3f;
    p = fmaf(p, f, 9.61011902e-3f);
    p = fmaf(p, f, 5.55036420e-2f);
    p = fmaf(p, f, 2.40226522e-1f);
    p = fmaf(p, f, 6.93147182e-1f);
    p = fmaf(p, f, 1.0f);
    return __int_as_float(__float_as_int(p) + ((int)n << 23));
}

// ---- tf32 pre-rounding pass ----
__global__ void rnd_kernel(const float4* __restrict__ src, float4* __restrict__ dst, int n4){
    int i = blockIdx.x * blockDim.x + threadIdx.x;
    if (i < n4){
        float4 v = src[i];
        v.x = rtf(v.x); v.y = rtf(v.y); v.z = rtf(v.z); v.w = rtf(v.w);
        dst[i] = v;
    }
}

// ---------------------------------------------------------------------------
// TF32 GEMM, cp.async 2-stage double buffer, static smem (40KB).
// ---------------------------------------------------------------------------
__global__ void __launch_bounds__(256) gemm_ca(
    const float* __restrict__ A, const float* __restrict__ B,
    const float* __restrict__ bias, float* __restrict__ out,
    const float* __restrict__ alphap,
    int Kdim, long long sA, long long sB, long long sO,
    int fmode, int outMode, int L, int ldo, int ostride, int ooff, int roundOut)
{
    __shared__ float smA[2][2560];
    __shared__ float smB[2][2560];
    const int z = blockIdx.z;
    A += (size_t)z * sA;  B += (size_t)z * sB;  out += (size_t)z * sO;

    const int tid = threadIdx.x, w = tid >> 5, t = tid & 31;
    const int wm = w & 1, wn = w >> 1;
    const int m0 = blockIdx.y * 128, n0 = blockIdx.x * 128;
    const int NK = Kdim >> 4;

    auto issue = [&](int kt, int s){
#pragma unroll
        for (int c = tid; c < 512; c += 256){
            int m = c >> 2, kc = (c & 3) << 2;
            cp16(&smA[s][m*20 + kc], A + (size_t)(m0+m)*Kdim + kt*16 + kc);
        }
#pragma unroll
        for (int c = tid; c < 512; c += 256){
            int n = c >> 2, kc = (c & 3) << 2;
            cp16(&smB[s][n*20 + kc], B + (size_t)(n0+n)*Kdim + kt*16 + kc);
        }
    };

    issue(0, 0); CP_COMMIT;

    float acc[4][4][4] = {};
    for (int kt = 0; kt < NK; kt++){
        if (kt + 1 < NK) issue(kt + 1, (kt + 1) & 1);
        CP_COMMIT;
        CP_WAIT1;
        __syncthreads();
        const float* cA = smA[kt & 1];
        const float* cB = smB[kt & 1];
#pragma unroll
        for (int kk = 0; kk < 2; kk++){
            const int k0 = kk*8 + (t & 3);
            uint32_t af[4][4];
#pragma unroll
            for (int mt = 0; mt < 4; mt++){
                int r = wm*64 + mt*16 + (t >> 2);
                af[mt][0] = __float_as_uint(cA[ r     *20 + k0    ]);
                af[mt][1] = __float_as_uint(cA[(r + 8)*20 + k0    ]);
                af[mt][2] = __float_as_uint(cA[ r     *20 + k0 + 4]);
                af[mt][3] = __float_as_uint(cA[(r + 8)*20 + k0 + 4]);
            }
#pragma unroll
            for (int nt = 0; nt < 4; nt++){
                int n = wn*32 + nt*8 + (t >> 2);
                uint32_t b0 = __float_as_uint(cB[n*20 + k0    ]);
                uint32_t b1 = __float_as_uint(cB[n*20 + k0 + 4]);
#pragma unroll
                for (int mt = 0; mt < 4; mt++) mma8(acc[mt][nt], af[mt], b0, b1);
            }
        }
        __syncthreads();
    }

    float f = 1.0f;
    if (fmode){
        float a = 1.0f / (1.0f + expf(-alphap[0]));
        f = (fmode == 1 ? a : 1.0f - a) * 0.125f;
    }
#pragma unroll
    for (int mt = 0; mt < 4; mt++){
#pragma unroll
        for (int nt = 0; nt < 4; nt++){
            int gn = n0 + wn*32 + nt*8 + (t & 3)*2;
            float bi0 = bias ? bias[gn]   : 0.0f;
            float bi1 = bias ? bias[gn+1] : 0.0f;
#pragma unroll
            for (int hh = 0; hh < 2; hh++){
                int gm = m0 + wm*64 + mt*16 + (t >> 2) + hh*8;
                float o0 = f * (acc[mt][nt][hh*2  ] + bi0);
                float o1 = f * (acc[mt][nt][hh*2+1] + bi1);
                if (roundOut){ o0 = rtf(o0); o1 = rtf(o1); }
                size_t idx;
                if (outMode == 0) idx = (size_t)gm * ldo + gn;
                else {
                    int b = gm / L, l = gm - b * L;
                    idx = ((size_t)((b*NH + (gn >> 6)) * L + l)) * ostride + ooff + (gn & 63);
                }
                *(float2*)&out[idx] = make_float2(o0, o1);
            }
        }
    }
}

// ---------------------------------------------------------------------------
// FUSED scores + online softmax.
// Block: 32 q-rows x full 1024 p (8 chunks of 128), K=128.
// A (QKd 32x128) resident in smem; B (KQp) streamed 2-stage, chunk-major.
// exp values kept in registers (ex[8][16]); exact attn -> attnOut,
// tf32-rounded -> attnR. Warp grid: wm=w&1 (16 q), wn=w>>1 (32 p).
// ---------------------------------------------------------------------------
__global__ void __launch_bounds__(256) attn_fused(
    const float* __restrict__ QKd, const float* __restrict__ KQp,
    float* __restrict__ attnOut, float* __restrict__ attnR)
{
    __shared__ float sA[32*132];        // [q][k], banks 4r+k: conflict-free
    __shared__ float sB[2][128*20];     // [p][k] stage
    __shared__ float redm[32][4];
    __shared__ float reds[32][4];

    const int bh = blockIdx.y, q0 = blockIdx.x * 32;
    const int tid = threadIdx.x, w = tid >> 5, t = tid & 31;
    const int wm = w & 1, wn = w >> 1;
    const int r0 = t >> 2, qlane = t & 3;
    const float* Ab = QKd + ((size_t)bh*LD + q0)*128;
    const float* Bb = KQp + (size_t)bh*LP*128;

    // Load resident A tile (32x128) -> sA
    for (int c = tid; c < 1024; c += 256){
        int m = c >> 5, k4 = (c & 31) << 2;
        cp16(&sA[m*132 + k4], Ab + (size_t)m*128 + k4);
    }
    auto issueB = [&](int gs){       // gs = chunk*8 + step
        int ch = gs >> 3, st = gs & 7;
#pragma unroll
        for (int c = tid; c < 512; c += 256){
            int p = c >> 2, kc = (c & 3) << 2;
            cp16(&sB[gs & 1][p*20 + kc], Bb + (size_t)(ch*128 + p)*128 + st*16 + kc);
        }
    };
    issueB(0); CP_COMMIT;            // group 0 = A tile + B stage 0

    float Mrun0 = -1e30f, Mrun1 = -1e30f, Srun0 = 0.0f, Srun1 = 0.0f;
    float ex[8][16];

#pragma unroll
    for (int ch = 0; ch < 8; ch++){
        float acc[4][4] = {};
        for (int st = 0; st < 8; st++){
            int gs = ch*8 + st;
            if (gs + 1 < 64) issueB(gs + 1);
            CP_COMMIT;
            CP_WAIT1;
            __syncthreads();
            const float* cB = sB[gs & 1];
#pragma unroll
            for (int kk = 0; kk < 2; kk++){
                const int kb = kk*8 + qlane;
                const int ka = st*16 + kb;
                uint32_t af[4];
                int r = wm*16 + r0;
                af[0] = __float_as_uint(sA[ r     *132 + ka    ]);
                af[1] = __float_as_uint(sA[(r + 8)*132 + ka    ]);
                af[2] = __float_as_uint(sA[ r     *132 + ka + 4]);
                af[3] = __float_as_uint(sA[(r + 8)*132 + ka + 4]);
#pragma unroll
                for (int nt = 0; nt < 4; nt++){
                    int n = wn*32 + nt*8 + r0;
                    uint32_t b0 = __float_as_uint(cB[n*20 + kb    ]);
                    uint32_t b1 = __float_as_uint(cB[n*20 + kb + 4]);
                    mma8(acc[nt], af, b0, b1);
                }
            }
            __syncthreads();
        }

        // ---- online softmax update for this chunk ----
        float mA = -1e30f, mB = -1e30f;
#pragma unroll
        for (int nt = 0; nt < 4; nt++){
            mA = fmaxf(mA, fmaxf(acc[nt][0], acc[nt][1]));
            mB = fmaxf(mB, fmaxf(acc[nt][2], acc[nt][3]));
        }
        mA = fmaxf(mA, __shfl_xor_sync(0xFFFFFFFFu, mA, 1));
        mA = fmaxf(mA, __shfl_xor_sync(0xFFFFFFFFu, mA, 2));
        mB = fmaxf(mB, __shfl_xor_sync(0xFFFFFFFFu, mB, 1));
        mB = fmaxf(mB, __shfl_xor_sync(0xFFFFFFFFu, mB, 2));
        if (qlane == 0){
            redm[wm*16 + r0    ][wn] = mA;
            redm[wm*16 + r0 + 8][wn] = mB;
        }
        __syncthreads();
        mA = fmaxf(fmaxf(redm[wm*16 + r0][0],     redm[wm*16 + r0][1]),
                   fmaxf(redm[wm*16 + r0][2],     redm[wm*16 + r0][3]));
        mB = fmaxf(fmaxf(redm[wm*16 + r0 + 8][0], redm[wm*16 + r0 + 8][1]),
                   fmaxf(redm[wm*16 + r0 + 8][2], redm[wm*16 + r0 + 8][3]));

        float Mn0 = fmaxf(Mrun0, mA), Mn1 = fmaxf(Mrun1, mB);
        float f0 = fexp(Mrun0 - Mn0), f1 = fexp(Mrun1 - Mn1);
        Mrun0 = Mn0; Mrun1 = Mn1;
        Srun0 *= f0; Srun1 *= f1;
#pragma unroll
        for (int cc = 0; cc < 8; cc++){
            if (cc < ch){
#pragma unroll
                for (int nt = 0; nt < 4; nt++){
                    ex[cc][nt*4+0] *= f0; ex[cc][nt*4+1] *= f0;
                    ex[cc][nt*4+2] *= f1; ex[cc][nt*4+3] *= f1;
                }
            }
        }
        float s0 = 0.0f, s1 = 0.0f;
#pragma unroll
        for (int nt = 0; nt < 4; nt++){
            float e0 = fexp(acc[nt][0] - Mn0), e1 = fexp(acc[nt][1] - Mn0);
            float e2 = fexp(acc[nt][2] - Mn1), e3 = fexp(acc[nt][3] - Mn1);
            ex[ch][nt*4+0] = e0; ex[ch][nt*4+1] = e1;
            ex[ch][nt*4+2] = e2; ex[ch][nt*4+3] = e3;
            s0 += e0 + e1; s1 += e2 + e3;
        }
        s0 += __shfl_xor_sync(0xFFFFFFFFu, s0, 1);
        s0 += __shfl_xor_sync(0xFFFFFFFFu, s0, 2);
        s1 += __shfl_xor_sync(0xFFFFFFFFu, s1, 1);
        s1 += __shfl_xor_sync(0xFFFFFFFFu, s1, 2);
        if (qlane == 0){
            reds[wm*16 + r0    ][wn] = s0;
            reds[wm*16 + r0 + 8][wn] = s1;
        }
        __syncthreads();
        s0 = reds[wm*16 + r0][0]     + reds[wm*16 + r0][1]
           + reds[wm*16 + r0][2]     + reds[wm*16 + r0][3];
        s1 = reds[wm*16 + r0 + 8][0] + reds[wm*16 + r0 + 8][1]
           + reds[wm*16 + r0 + 8][2] + reds[wm*16 + r0 + 8][3];
        Srun0 += s0; Srun1 += s1;
    }

    const float inv0 = 1.0f / Srun0, inv1 = 1.0f / Srun1;
    const int qA = q0 + wm*16 + r0, qB = qA + 8;
#pragma unroll
    for (int ch = 0; ch < 8; ch++){
#pragma unroll
        for (int nt = 0; nt < 4; nt++){
            int p = ch*128 + wn*32 + nt*8 + 2*qlane;
            size_t iA = ((size_t)bh*LD + qA)*LP + p;
            size_t iB = ((size_t)bh*LD + qB)*LP + p;
            float a0 = ex[ch][nt*4+0]*inv0, a1 = ex[ch][nt*4+1]*inv0;
            float b0 = ex[ch][nt*4+2]*inv1, b1 = ex[ch][nt*4+3]*inv1;
            *(float2*)&attnOut[iA] = make_float2(a0, a1);
            *(float2*)&attnOut[iB] = make_float2(b0, b1);
            *(float2*)&attnR[iA]   = make_float2(rtf(a0), rtf(a1));
            *(float2*)&attnR[iB]   = make_float2(rtf(b0), rtf(b1));
        }
    }
}

// ---------------------------------------------------------------------------
// ctx TF32 cp.async 3-stage (static smem). Inputs pre-rounded (g_aR, g_V*).
// ---------------------------------------------------------------------------
template<int TRANSA>
__global__ void __launch_bounds__(256) ctx_ca(
    const float* __restrict__ attn, const float* __restrict__ V,
    float* __restrict__ out, int Kdim, int Lout)
{
    const int ASZ = TRANSA ? 2176 : 2560;
    __shared__ float sm[3*2560 + 3*1152];
    float* smB = sm + 3*ASZ;

    const int z = blockIdx.z, b = z >> 3, h = z & 7;
    const int m0 = blockIdx.y * 128;
    const float* A  = attn + (size_t)z * LD * LP;
    const float* Vb = V    + (size_t)z * Kdim * 64;

    const int tid = threadIdx.x, w = tid >> 5, t = tid & 31;
    const int wm = w & 1, wn = w >> 1;
    const int NK = Kdim >> 4;

    auto issue = [&](int kt, int s){
        if (TRANSA == 0){
#pragma unroll
            for (int c = tid; c < 512; c += 256){
                int m = c >> 2, kc = (c & 3) << 2;
                cp16(sm + s*ASZ + m*20 + kc, A + (size_t)(m0+m)*LP + kt*16 + kc);
            }
        } else {
#pragma unroll
            for (int c = tid; c < 512; c += 256){
                int k = c >> 5, m4 = (c & 31) << 2;
                cp16(sm + s*ASZ + k*136 + m4, A + (size_t)(kt*16 + k)*LP + m0 + m4);
            }
        }
        { int c = tid; int k = c >> 4, cc = (c & 15) << 2;
          cp16(smB + s*1152 + k*72 + cc, Vb + (size_t)(kt*16 + k)*64 + cc); }
    };

    issue(0, 0); CP_COMMIT;
    issue(1, 1); CP_COMMIT;

    float acc[4][2][4] = {};
    for (int kt = 0; kt < NK; kt++){
        CP_WAIT1; __syncthreads();
        if (kt + 2 < NK) issue(kt + 2, (kt + 2) % 3);
        CP_COMMIT;
        const float* cA = sm + (kt % 3) * ASZ;
        const float* cB = smB + (kt % 3) * 1152;
#pragma unroll
        for (int kk = 0; kk < 2; kk++){
            const int k0 = kk*8 + (t & 3);
            uint32_t af[4][4];
#pragma unroll
            for (int mt = 0; mt < 4; mt++){
                int r = wm*64 + mt*16 + (t >> 2);
                if (TRANSA == 0){
                    af[mt][0] = __float_as_uint(cA[ r     *20 + k0    ]);
                    af[mt][1] = __float_as_uint(cA[(r + 8)*20 + k0    ]);
                    af[mt][2] = __float_as_uint(cA[ r     *20 + k0 + 4]);
                    af[mt][3] = __float_as_uint(cA[(r + 8)*20 + k0 + 4]);
                } else {
                    af[mt][0] = __float_as_uint(cA[ k0     *136 + r    ]);
                    af[mt][1] = __float_as_uint(cA[ k0     *136 + r + 8]);
                    af[mt][2] = __float_as_uint(cA[(k0 + 4)*136 + r    ]);
                    af[mt][3] = __float_as_uint(cA[(k0 + 4)*136 + r + 8]);
                }
            }
#pragma unroll
            for (int nt = 0; nt < 2; nt++){
                int n = wn*16 + nt*8 + (t >> 2);
                uint32_t b0 = __float_as_uint(cB[ k0     *72 + n]);
                uint32_t b1 = __float_as_uint(cB[(k0 + 4)*72 + n]);
#pragma unroll
                for (int mt = 0; mt < 4; mt++) mma8(acc[mt][nt], af[mt], b0, b1);
            }
        }
        __syncthreads();
    }

#pragma unroll
    for (int mt = 0; mt < 4; mt++){
#pragma unroll
        for (int nt = 0; nt < 2; nt++){
            int gn = wn*16 + nt*8 + (t & 3)*2;
#pragma unroll
            for (int hh = 0; hh < 2; hh++){
                int gm = m0 + wm*64 + mt*16 + (t >> 2) + hh*8;
                size_t idx = ((size_t)(b*Lout + gm))*512 + h*64 + gn;
                *(float2*)&out[idx] = make_float2(rtf(acc[mt][nt][hh*2]), rtf(acc[mt][nt][hh*2+1]));
            }
        }
    }
}

// ---------------------------------------------------------------------------
extern "C" void kernel_launch(void* const* d_in, const int* in_sizes, int n_in,
                              void* d_out, int out_size) {
    const float* drug    = (const float*)d_in[0];
    const float* protein = (const float*)d_in[1];
    const float* Wqd = (const float*)d_in[2];  const float* bqd = (const float*)d_in[3];
    const float* Wkp = (const float*)d_in[4];  const float* bkp = (const float*)d_in[5];
    const float* Wvp = (const float*)d_in[6];  const float* bvp = (const float*)d_in[7];
    const float* Wqp = (const float*)d_in[8];  const float* bqp = (const float*)d_in[9];
    const float* Wkd = (const float*)d_in[10]; const float* bkd = (const float*)d_in[11];
    const float* Wvd = (const float*)d_in[12]; const float* bvd = (const float*)d_in[13];
    const float* alpha = (const float*)d_in[14];
    const float* Wod = (const float*)d_in[15]; const float* bod = (const float*)d_in[16];
    const float* Wop = (const float*)d_in[17]; const float* bop = (const float*)d_in[18];

    float* out      = (float*)d_out;
    float* out_attn = out;
    float* out_cd   = out + (size_t)256*LD*LP;
    float* out_cp   = out_cd + (size_t)BB*LD*512;

    float *rd, *rp, *rw, *qkd, *kqp, *vd, *vp, *aR, *cd, *cp;
    cudaGetSymbolAddress((void**)&rd,  g_rd);
    cudaGetSymbolAddress((void**)&rp,  g_rp);
    cudaGetSymbolAddress((void**)&rw,  g_W);
    cudaGetSymbolAddress((void**)&qkd, g_QKd);
    cudaGetSymbolAddress((void**)&kqp, g_KQp);
    cudaGetSymbolAddress((void**)&vd,  g_Vd);
    cudaGetSymbolAddress((void**)&vp,  g_Vp);
    cudaGetSymbolAddress((void**)&aR,  g_aR);
    cudaGetSymbolAddress((void**)&cd,  g_cd);
    cudaGetSymbolAddress((void**)&cp,  g_cp);

    const int WSZ = 512*512, W4 = WSZ/4;
    // Pre-round inputs and weights into scratch.
    rnd_kernel<<<(BB*LD*512/4 + 255)/256, 256>>>((const float4*)drug,    (float4*)rd, BB*LD*512/4);
    rnd_kernel<<<(BB*LP*512/4 + 255)/256, 256>>>((const float4*)protein, (float4*)rp, BB*LP*512/4);
    const float* Ws[8] = {Wqd, Wkd, Wvd, Wkp, Wqp, Wvp, Wod, Wop};
    for (int i = 0; i < 8; i++)
        rnd_kernel<<<(W4 + 255)/256, 256>>>((const float4*)Ws[i], (float4*)(rw + (size_t)i*WSZ), W4);

    // Projections (rounded outputs). Qd: sig(a)/8; Kd: (1-sig(a))/8.
    gemm_ca<<<dim3(4,64),  256>>>(rd, rw + 0*WSZ, bqd, qkd, alpha, 512,0,0,0, 1,1, LD, 0, 128, 0, 1);
    gemm_ca<<<dim3(4,64),  256>>>(rd, rw + 1*WSZ, bkd, qkd, alpha, 512,0,0,0, 2,1, LD, 0, 128, 64, 1);
    gemm_ca<<<dim3(4,64),  256>>>(rd, rw + 2*WSZ, bvd, vd,  alpha, 512,0,0,0, 0,1, LD, 0, 64, 0, 1);
    gemm_ca<<<dim3(4,256), 256>>>(rp, rw + 3*WSZ, bkp, kqp, alpha, 512,0,0,0, 0,1, LP, 0, 128, 0, 1);
    gemm_ca<<<dim3(4,256), 256>>>(rp, rw + 4*WSZ, bqp, kqp, alpha, 512,0,0,0, 0,1, LP, 0, 128, 64, 1);
    gemm_ca<<<dim3(4,256), 256>>>(rp, rw + 5*WSZ, bvp, vp,  alpha, 512,0,0,0, 0,1, LP, 0, 64, 0, 1);

    // Fused scores + online softmax: exact attn -> d_out, rounded -> aR.
    attn_fused<<<dim3(8, 256), 256>>>(qkd, kqp, out_attn, aR);

    // Contexts from rounded attn + rounded V, rounded outputs.
    ctx_ca<0><<<dim3(1,2,256), 256>>>(aR, vp, cd, LP, LD);
    ctx_ca<1><<<dim3(1,8,256), 256>>>(aR, vd, cp, LD, LP);

    // Output projections (exact into d_out).
    gemm_ca<<<dim3(4,64),  256>>>(cd, rw + 6*WSZ, bod, out_cd, alpha, 512,0,0,0, 0,0, LD, 512, 0, 0, 0);
    gemm_ca<<<dim3(4,256), 256>>>(cp, rw + 7*WSZ, bop, out_cp, alpha, 512,0,0,0, 0,0, LP, 512, 0, 0, 0);
}

// round 9
// speedup vs baseline: 1.1933x; 1.1933x over previous
#include <cuda_runtime.h>
#include <cstdint>
#include <math.h>

#define BB 32
#define LD 256
#define LP 1024
#define NH 8

// ---- scratch (device globals; allocations forbidden) ----
__device__ float g_rd [(size_t)BB*LD*512];     // rounded drug
__device__ float g_rp [(size_t)BB*LP*512];     // rounded protein
__device__ float g_W  [(size_t)8*512*512];     // rounded weights
__device__ float g_QKd[(size_t)256*LD*128];    // [bh][q][Qd|Kd] scaled, rounded
__device__ float g_KQp[(size_t)256*LP*128];    // [bh][p][Kp|Qp] rounded
__device__ float g_Vd [(size_t)256*LD*64];     // rounded
__device__ float g_Vp [(size_t)256*LP*64];     // rounded
__device__ float g_cd [(size_t)BB*LD*512];     // rounded ctx_d
__device__ float g_cp [(size_t)BB*LP*512];     // rounded ctx_p

__device__ __forceinline__ float rtf(float x){
    uint32_t u = __float_as_uint(x);
    return __uint_as_float((u + 0x1000u) & 0xFFFFE000u);
}
__device__ __forceinline__ void cp16(void* s, const void* g){
    uint32_t sa = (uint32_t)__cvta_generic_to_shared(s);
    asm volatile("cp.async.cg.shared.global [%0], [%1], 16;\n" :: "r"(sa), "l"(g));
}
#define CP_COMMIT asm volatile("cp.async.commit_group;\n")
#define CP_WAIT0  asm volatile("cp.async.wait_group 0;\n")
#define CP_WAIT1  asm volatile("cp.async.wait_group 1;\n")

__device__ __forceinline__ void mma8(float* c, const uint32_t* a, uint32_t b0, uint32_t b1){
    asm volatile("mma.sync.aligned.m16n8k8.row.col.f32.tf32.tf32.f32 "
        "{%0,%1,%2,%3}, {%4,%5,%6,%7}, {%8,%9}, {%0,%1,%2,%3};\n"
        : "+f"(c[0]), "+f"(c[1]), "+f"(c[2]), "+f"(c[3])
        : "r"(a[0]), "r"(a[1]), "r"(a[2]), "r"(a[3]), "r"(b0), "r"(b1));
}
__device__ __forceinline__ float fexp(float x){
    x = fmaxf(x, -80.0f);
    float t = x * 1.44269504089f;
    float n = rintf(t);
    float f = t - n;
    float p =           1.33336621e-3f;
    p = fmaf(p, f, 9.61011902e-3f);
    p = fmaf(p, f, 5.55036420e-2f);
    p = fmaf(p, f, 2.40226522e-1f);
    p = fmaf(p, f, 6.93147182e-1f);
    p = fmaf(p, f, 1.0f);
    return __int_as_float(__float_as_int(p) + ((int)n << 23));
}

// ---- tf32 pre-rounding pass ----
__global__ void rnd_kernel(const float4* __restrict__ src, float4* __restrict__ dst, int n4){
    int i = blockIdx.x * blockDim.x + threadIdx.x;
    if (i < n4){
        float4 v = src[i];
        v.x = rtf(v.x); v.y = rtf(v.y); v.z = rtf(v.z); v.w = rtf(v.w);
        dst[i] = v;
    }
}

// ---------------------------------------------------------------------------
// TF32 GEMM, cp.async 2-stage double buffer, static smem (40KB).
// Single-sync pipeline: {wait0; sync; issue(kt+1); commit; mma(kt)}.
//  - copy kt+1 overlaps mma kt (different stage by parity)
//  - top sync orders last iter's readers before this iter's writes
// ---------------------------------------------------------------------------
__global__ void __launch_bounds__(256) gemm_ca(
    const float* __restrict__ A, const float* __restrict__ B,
    const float* __restrict__ bias, float* __restrict__ out,
    const float* __restrict__ alphap,
    int Kdim, long long sA, long long sB, long long sO,
    int fmode, int outMode, int L, int ldo, int ostride, int ooff, int roundOut)
{
    __shared__ float smA[2][2560];
    __shared__ float smB[2][2560];
    const int z = blockIdx.z;
    A += (size_t)z * sA;  B += (size_t)z * sB;  out += (size_t)z * sO;

    const int tid = threadIdx.x, w = tid >> 5, t = tid & 31;
    const int wm = w & 1, wn = w >> 1;
    const int m0 = blockIdx.y * 128, n0 = blockIdx.x * 128;
    const int NK = Kdim >> 4;

    auto issue = [&](int kt, int s){
#pragma unroll
        for (int c = tid; c < 512; c += 256){
            int m = c >> 2, kc = (c & 3) << 2;
            cp16(&smA[s][m*20 + kc], A + (size_t)(m0+m)*Kdim + kt*16 + kc);
        }
#pragma unroll
        for (int c = tid; c < 512; c += 256){
            int n = c >> 2, kc = (c & 3) << 2;
            cp16(&smB[s][n*20 + kc], B + (size_t)(n0+n)*Kdim + kt*16 + kc);
        }
    };

    issue(0, 0); CP_COMMIT;

    float acc[4][4][4] = {};
    for (int kt = 0; kt < NK; kt++){
        CP_WAIT0;               // stage kt complete (issued last iteration)
        __syncthreads();        // also orders last iter's reads before new writes
        if (kt + 1 < NK) issue(kt + 1, (kt + 1) & 1);
        CP_COMMIT;
        const float* cA = smA[kt & 1];
        const float* cB = smB[kt & 1];
#pragma unroll
        for (int kk = 0; kk < 2; kk++){
            const int k0 = kk*8 + (t & 3);
            uint32_t af[4][4];
#pragma unroll
            for (int mt = 0; mt < 4; mt++){
                int r = wm*64 + mt*16 + (t >> 2);
                af[mt][0] = __float_as_uint(cA[ r     *20 + k0    ]);
                af[mt][1] = __float_as_uint(cA[(r + 8)*20 + k0    ]);
                af[mt][2] = __float_as_uint(cA[ r     *20 + k0 + 4]);
                af[mt][3] = __float_as_uint(cA[(r + 8)*20 + k0 + 4]);
            }
#pragma unroll
            for (int nt = 0; nt < 4; nt++){
                int n = wn*32 + nt*8 + (t >> 2);
                uint32_t b0 = __float_as_uint(cB[n*20 + k0    ]);
                uint32_t b1 = __float_as_uint(cB[n*20 + k0 + 4]);
#pragma unroll
                for (int mt = 0; mt < 4; mt++) mma8(acc[mt][nt], af[mt], b0, b1);
            }
        }
    }

    float f = 1.0f;
    if (fmode){
        float a = 1.0f / (1.0f + expf(-alphap[0]));
        f = (fmode == 1 ? a : 1.0f - a) * 0.125f;
    }
#pragma unroll
    for (int mt = 0; mt < 4; mt++){
#pragma unroll
        for (int nt = 0; nt < 4; nt++){
            int gn = n0 + wn*32 + nt*8 + (t & 3)*2;
            float bi0 = bias ? bias[gn]   : 0.0f;
            float bi1 = bias ? bias[gn+1] : 0.0f;
#pragma unroll
            for (int hh = 0; hh < 2; hh++){
                int gm = m0 + wm*64 + mt*16 + (t >> 2) + hh*8;
                float o0 = f * (acc[mt][nt][hh*2  ] + bi0);
                float o1 = f * (acc[mt][nt][hh*2+1] + bi1);
                if (roundOut){ o0 = rtf(o0); o1 = rtf(o1); }
                size_t idx;
                if (outMode == 0) idx = (size_t)gm * ldo + gn;
                else {
                    int b = gm / L, l = gm - b * L;
                    idx = ((size_t)((b*NH + (gn >> 6)) * L + l)) * ostride + ooff + (gn & 63);
                }
                *(float2*)&out[idx] = make_float2(o0, o1);
            }
        }
    }
}

// ---------------------------------------------------------------------------
// Row softmax over 1024 elems, in-place, exact output only (no MUFU).
// ctx kernels consume this directly; mma HW truncates fp32->tf32.
// ---------------------------------------------------------------------------
__global__ void __launch_bounds__(256) softmax_kernel(
    const float* __restrict__ S, float* __restrict__ out)
{
    const size_t row = blockIdx.x;
    const float* src = S + row * LP;
    float* dst = out + row * LP;
    const int tid = threadIdx.x;

    float4 v = *(const float4*)(src + tid*4);
    float m = fmaxf(fmaxf(v.x, v.y), fmaxf(v.z, v.w));
#pragma unroll
    for (int o = 16; o > 0; o >>= 1) m = fmaxf(m, __shfl_xor_sync(0xFFFFFFFFu, m, o));

    __shared__ float redm[8], reds[8];
    if ((tid & 31) == 0) redm[tid >> 5] = m;
    __syncthreads();
    float rm = redm[0];
#pragma unroll
    for (int i = 1; i < 8; i++) rm = fmaxf(rm, redm[i]);

    float e0 = fexp(v.x - rm), e1 = fexp(v.y - rm);
    float e2 = fexp(v.z - rm), e3 = fexp(v.w - rm);
    float s = e0 + e1 + e2 + e3;
#pragma unroll
    for (int o = 16; o > 0; o >>= 1) s += __shfl_xor_sync(0xFFFFFFFFu, s, o);
    if ((tid & 31) == 0) reds[tid >> 5] = s;
    __syncthreads();
    float tot = 0.0f;
#pragma unroll
    for (int i = 0; i < 8; i++) tot += reds[i];
    float inv = 1.0f / tot;
    *(float4*)(dst + tid*4) = make_float4(e0*inv, e1*inv, e2*inv, e3*inv);
}

// ---------------------------------------------------------------------------
// ctx TF32 cp.async 3-stage (static smem). A = exact attn from d_out
// (HW-truncated to tf32 in mma), V pre-rounded. Single sync per K-step.
// TRANSA=0 (ctx_d): A[m][k]=attn[q][p], K=1024; smem As[m(128)][20]
// TRANSA=1 (ctx_p): A[k][m]=attn[q][p] (m=p), K=256; smem As[k(16)][136]
// ---------------------------------------------------------------------------
template<int TRANSA>
__global__ void __launch_bounds__(256) ctx_ca(
    const float* __restrict__ attn, const float* __restrict__ V,
    float* __restrict__ out, int Kdim, int Lout)
{
    const int ASZ = TRANSA ? 2176 : 2560;
    __shared__ float sm[3*2560 + 3*1152];
    float* smB = sm + 3*ASZ;

    const int z = blockIdx.z, b = z >> 3, h = z & 7;
    const int m0 = blockIdx.y * 128;
    const float* A  = attn + (size_t)z * LD * LP;
    const float* Vb = V    + (size_t)z * Kdim * 64;

    const int tid = threadIdx.x, w = tid >> 5, t = tid & 31;
    const int wm = w & 1, wn = w >> 1;
    const int NK = Kdim >> 4;

    auto issue = [&](int kt, int s){
        if (TRANSA == 0){
#pragma unroll
            for (int c = tid; c < 512; c += 256){
                int m = c >> 2, kc = (c & 3) << 2;
                cp16(sm + s*ASZ + m*20 + kc, A + (size_t)(m0+m)*LP + kt*16 + kc);
            }
        } else {
#pragma unroll
            for (int c = tid; c < 512; c += 256){
                int k = c >> 5, m4 = (c & 31) << 2;
                cp16(sm + s*ASZ + k*136 + m4, A + (size_t)(kt*16 + k)*LP + m0 + m4);
            }
        }
        { int c = tid; int k = c >> 4, cc = (c & 15) << 2;
          cp16(smB + s*1152 + k*72 + cc, Vb + (size_t)(kt*16 + k)*64 + cc); }
    };

    issue(0, 0); CP_COMMIT;
    issue(1, 1); CP_COMMIT;

    float acc[4][2][4] = {};
    for (int kt = 0; kt < NK; kt++){
        CP_WAIT1;               // stage kt done (leaves only newest pending)
        __syncthreads();        // orders last iter's reads before new writes
        if (kt + 2 < NK) issue(kt + 2, (kt + 2) % 3);
        CP_COMMIT;
        const float* cA = sm + (kt % 3) * ASZ;
        const float* cB = smB + (kt % 3) * 1152;
#pragma unroll
        for (int kk = 0; kk < 2; kk++){
            const int k0 = kk*8 + (t & 3);
            uint32_t af[4][4];
#pragma unroll
            for (int mt = 0; mt < 4; mt++){
                int r = wm*64 + mt*16 + (t >> 2);
                if (TRANSA == 0){
                    af[mt][0] = __float_as_uint(cA[ r     *20 + k0    ]);
                    af[mt][1] = __float_as_uint(cA[(r + 8)*20 + k0    ]);
                    af[mt][2] = __float_as_uint(cA[ r     *20 + k0 + 4]);
                    af[mt][3] = __float_as_uint(cA[(r + 8)*20 + k0 + 4]);
                } else {
                    af[mt][0] = __float_as_uint(cA[ k0     *136 + r    ]);
                    af[mt][1] = __float_as_uint(cA[ k0     *136 + r + 8]);
                    af[mt][2] = __float_as_uint(cA[(k0 + 4)*136 + r    ]);
                    af[mt][3] = __float_as_uint(cA[(k0 + 4)*136 + r + 8]);
                }
            }
#pragma unroll
            for (int nt = 0; nt < 2; nt++){
                int n = wn*16 + nt*8 + (t >> 2);
                uint32_t b0 = __float_as_uint(cB[ k0     *72 + n]);
                uint32_t b1 = __float_as_uint(cB[(k0 + 4)*72 + n]);
#pragma unroll
                for (int mt = 0; mt < 4; mt++) mma8(acc[mt][nt], af[mt], b0, b1);
            }
        }
    }

#pragma unroll
    for (int mt = 0; mt < 4; mt++){
#pragma unroll
        for (int nt = 0; nt < 2; nt++){
            int gn = wn*16 + nt*8 + (t & 3)*2;
#pragma unroll
            for (int hh = 0; hh < 2; hh++){
                int gm = m0 + wm*64 + mt*16 + (t >> 2) + hh*8;
                size_t idx = ((size_t)(b*Lout + gm))*512 + h*64 + gn;
                *(float2*)&out[idx] = make_float2(rtf(acc[mt][nt][hh*2]), rtf(acc[mt][nt][hh*2+1]));
            }
        }
    }
}

// ---------------------------------------------------------------------------
extern "C" void kernel_launch(void* const* d_in, const int* in_sizes, int n_in,
                              void* d_out, int out_size) {
    const float* drug    = (const float*)d_in[0];
    const float* protein = (const float*)d_in[1];
    const float* Wqd = (const float*)d_in[2];  const float* bqd = (const float*)d_in[3];
    const float* Wkp = (const float*)d_in[4];  const float* bkp = (const float*)d_in[5];
    const float* Wvp = (const float*)d_in[6];  const float* bvp = (const float*)d_in[7];
    const float* Wqp = (const float*)d_in[8];  const float* bqp = (const float*)d_in[9];
    const float* Wkd = (const float*)d_in[10]; const float* bkd = (const float*)d_in[11];
    const float* Wvd = (const float*)d_in[12]; const float* bvd = (const float*)d_in[13];
    const float* alpha = (const float*)d_in[14];
    const float* Wod = (const float*)d_in[15]; const float* bod = (const float*)d_in[16];
    const float* Wop = (const float*)d_in[17]; const float* bop = (const float*)d_in[18];

    float* out      = (float*)d_out;
    float* out_attn = out;
    float* out_cd   = out + (size_t)256*LD*LP;
    float* out_cp   = out_cd + (size_t)BB*LD*512;

    float *rd, *rp, *rw, *qkd, *kqp, *vd, *vp, *cd, *cp;
    cudaGetSymbolAddress((void**)&rd,  g_rd);
    cudaGetSymbolAddress((void**)&rp,  g_rp);
    cudaGetSymbolAddress((void**)&rw,  g_W);
    cudaGetSymbolAddress((void**)&qkd, g_QKd);
    cudaGetSymbolAddress((void**)&kqp, g_KQp);
    cudaGetSymbolAddress((void**)&vd,  g_Vd);
    cudaGetSymbolAddress((void**)&vp,  g_Vp);
    cudaGetSymbolAddress((void**)&cd,  g_cd);
    cudaGetSymbolAddress((void**)&cp,  g_cp);

    const int WSZ = 512*512, W4 = WSZ/4;
    // Pre-round inputs and weights into scratch.
    rnd_kernel<<<(BB*LD*512/4 + 255)/256, 256>>>((const float4*)drug,    (float4*)rd, BB*LD*512/4);
    rnd_kernel<<<(BB*LP*512/4 + 255)/256, 256>>>((const float4*)protein, (float4*)rp, BB*LP*512/4);
    const float* Ws[8] = {Wqd, Wkd, Wvd, Wkp, Wqp, Wvp, Wod, Wop};
    for (int i = 0; i < 8; i++)
        rnd_kernel<<<(W4 + 255)/256, 256>>>((const float4*)Ws[i], (float4*)(rw + (size_t)i*WSZ), W4);

    // Projections (rounded outputs). Qd: sig(a)/8; Kd: (1-sig(a))/8.
    gemm_ca<<<dim3(4,64),  256>>>(rd, rw + 0*WSZ, bqd, qkd, alpha, 512,0,0,0, 1,1, LD, 0, 128, 0, 1);
    gemm_ca<<<dim3(4,64),  256>>>(rd, rw + 1*WSZ, bkd, qkd, alpha, 512,0,0,0, 2,1, LD, 0, 128, 64, 1);
    gemm_ca<<<dim3(4,64),  256>>>(rd, rw + 2*WSZ, bvd, vd,  alpha, 512,0,0,0, 0,1, LD, 0, 64, 0, 1);
    gemm_ca<<<dim3(4,256), 256>>>(rp, rw + 3*WSZ, bkp, kqp, alpha, 512,0,0,0, 0,1, LP, 0, 128, 0, 1);
    gemm_ca<<<dim3(4,256), 256>>>(rp, rw + 4*WSZ, bqp, kqp, alpha, 512,0,0,0, 0,1, LP, 0, 128, 64, 1);
    gemm_ca<<<dim3(4,256), 256>>>(rp, rw + 5*WSZ, bvp, vp,  alpha, 512,0,0,0, 0,1, LP, 0, 64, 0, 1);

    // Scores: [Qd|Kd]@[Kp|Qp]^T, K=128, exact into attn region; softmax in place.
    gemm_ca<<<dim3(8,2,256), 256>>>(qkd, kqp, nullptr, out_attn, alpha,
                                    128, (long long)LD*128, (long long)LP*128,
                                    (long long)LD*LP, 0,0, LD, LP, 0, 0, 0);
    softmax_kernel<<<256*LD, 256>>>(out_attn, out_attn);

    // Contexts read exact attn from d_out (HW tf32 truncation); V pre-rounded.
    ctx_ca<0><<<dim3(1,2,256), 256>>>(out_attn, vp, cd, LP, LD);
    ctx_ca<1><<<dim3(1,8,256), 256>>>(out_attn, vd, cp, LD, LP);

    // Output projections (exact into d_out).
    gemm_ca<<<dim3(4,64),  256>>>(cd, rw + 6*WSZ, bod, out_cd, alpha, 512,0,0,0, 0,0, LD, 512, 0, 0, 0);
    gemm_ca<<<dim3(4,256), 256>>>(cp, rw + 7*WSZ, bop, out_cp, alpha, 512,0,0,0, 0,0, LP, 512, 0, 0, 0);
}